// round 1
// baseline (speedup 1.0000x reference)
#include <cuda_runtime.h>
#include <math.h>

// ---------------- problem constants ----------------
#define D_MODEL 512
#define SEQ     1024
#define BATCH   8
#define NHEADS  8
#define UDIM    64
#define FF      2048
#define TOK     (BATCH*SEQ)          // 8192
#define LN_EPS  1e-3f

// ---------------- scratch (static device, allocation-guard safe) -------------
__device__ float g_Wq[D_MODEL*D_MODEL];                    //   1 MB
__device__ float g_Wk[D_MODEL*D_MODEL];                    //   1 MB
__device__ float g_Wv[D_MODEL*NHEADS*D_MODEL];             //   8 MB
__device__ float g_Q [TOK*D_MODEL];                        //  16 MB
__device__ float g_Kb[TOK*D_MODEL];                        //  16 MB
__device__ float g_V [TOK*NHEADS*D_MODEL];                 // 128 MB
__device__ float g_S [(size_t)BATCH*NHEADS*SEQ*SEQ];       // 256 MB
__device__ float g_A [TOK*NHEADS*D_MODEL];                 // 128 MB
__device__ float g_Mha[TOK*D_MODEL];                       //  16 MB
__device__ float g_H [TOK*D_MODEL];                        //  16 MB
__device__ float g_F1[TOK*FF];                             //  64 MB
__device__ float g_F2[TOK*D_MODEL];                        //  16 MB

// ---------------- weight pack: [H,D,U] -> [D, H*U] ----------------
__global__ void pack_w(const float* __restrict__ in, float* __restrict__ out,
                       int H, int D, int U) {
    int i = blockIdx.x * blockDim.x + threadIdx.x;
    int total = H * D * U;
    if (i >= total) return;
    int u = i % U;
    int d = (i / U) % D;
    int h = i / (U * D);
    out[d * (H * U) + h * U + u] = in[i];
}

// ---------------- SGEMM 128x128x8, 256 threads, 8x8 microtile ----------------
// C[z][m][n] = sum_k A[z][m][k] * Bt(k,n)   (Bt = B or B^T per TRANSB)
// per-z offsets: off = (z/HB)*outer + (z%HB)*inner  (covers all our batchings)
// requires: M%128==0, N%128==0, K%8==0, all lds & offsets %4==0
template<bool TRANSB>
__global__ void __launch_bounds__(256, 2) gemm128(
    const float* __restrict__ A, const float* __restrict__ B, float* __restrict__ C,
    int M, int N, int K, int lda, int ldb, int ldc,
    long long aOut, long long aIn, long long bOut, long long bIn,
    long long cOut, long long cIn, int HB,
    const float* __restrict__ bias, int relu)
{
    int z  = blockIdx.z;
    int zo = z / HB, zi = z % HB;
    A += zo * aOut + (long long)zi * aIn;
    B += zo * bOut + (long long)zi * bIn;
    C += zo * cOut + (long long)zi * cIn;

    __shared__ float As[8][128];
    __shared__ float Bs[8][128];

    const int tid = threadIdx.x;
    const int bm  = blockIdx.y * 128;
    const int bn  = blockIdx.x * 128;
    const int tr  = (tid >> 4) << 3;   // row of 8x8 microtile
    const int tc  = (tid & 15) << 3;   // col of 8x8 microtile

    float acc[8][8];
#pragma unroll
    for (int i = 0; i < 8; i++)
#pragma unroll
        for (int j = 0; j < 8; j++) acc[i][j] = 0.f;

    // A tile load mapping: 128 rows x 8 cols = 256 float4
    const int arow = tid >> 1;            // 0..127
    const int ac4  = (tid & 1) << 2;      // 0 or 4
    // B tile NN mapping: 8 rows x 128 cols = 256 float4
    const int brow = tid >> 5;            // 0..7
    const int bcol = (tid & 31) << 2;     // 0..124

    const float* Aptr = A + (long long)(bm + arow) * lda + ac4;
    const float* BptrT = TRANSB ? (B + (long long)(bn + arow) * ldb + ac4) : B;
    const float* BptrN = TRANSB ? B : (B + (long long)brow * ldb + bn + bcol);

    for (int k0 = 0; k0 < K; k0 += 8) {
        float4 av = *(const float4*)(Aptr + k0);
        As[ac4 + 0][arow] = av.x;
        As[ac4 + 1][arow] = av.y;
        As[ac4 + 2][arow] = av.z;
        As[ac4 + 3][arow] = av.w;
        if (TRANSB) {
            float4 bv = *(const float4*)(BptrT + k0);
            Bs[ac4 + 0][arow] = bv.x;
            Bs[ac4 + 1][arow] = bv.y;
            Bs[ac4 + 2][arow] = bv.z;
            Bs[ac4 + 3][arow] = bv.w;
        } else {
            float4 bv = *(const float4*)(BptrN + (long long)k0 * ldb);
            *(float4*)&Bs[brow][bcol] = bv;
        }
        __syncthreads();
#pragma unroll
        for (int kk = 0; kk < 8; kk++) {
            float4 a0 = *(const float4*)&As[kk][tr];
            float4 a1 = *(const float4*)&As[kk][tr + 4];
            float4 b0 = *(const float4*)&Bs[kk][tc];
            float4 b1 = *(const float4*)&Bs[kk][tc + 4];
            float ar[8] = {a0.x, a0.y, a0.z, a0.w, a1.x, a1.y, a1.z, a1.w};
            float br[8] = {b0.x, b0.y, b0.z, b0.w, b1.x, b1.y, b1.z, b1.w};
#pragma unroll
            for (int i = 0; i < 8; i++)
#pragma unroll
                for (int j = 0; j < 8; j++)
                    acc[i][j] = fmaf(ar[i], br[j], acc[i][j]);
        }
        __syncthreads();
    }

    // epilogue: optional bias (per-n) + relu, vectorized stores
#pragma unroll
    for (int i = 0; i < 8; i++) {
        float v[8];
#pragma unroll
        for (int j = 0; j < 8; j++) {
            float t = acc[i][j];
            if (bias) t += bias[bn + tc + j];
            if (relu) t = fmaxf(t, 0.f);
            v[j] = t;
        }
        float* crow = C + (long long)(bm + tr + i) * ldc + bn + tc;
        *(float4*)(crow)     = make_float4(v[0], v[1], v[2], v[3]);
        *(float4*)(crow + 4) = make_float4(v[4], v[5], v[6], v[7]);
    }
}

// ---------------- row softmax over 1024 cols (with scale) ----------------
__global__ void softmax_1024(float* __restrict__ S, float scale) {
    long long row = blockIdx.x;
    float* p = S + row * 1024;
    int t = threadIdx.x;                       // 256 threads x 4 elems
    float4 v = *(float4*)(p + t * 4);
    v.x *= scale; v.y *= scale; v.z *= scale; v.w *= scale;

    __shared__ float red[256];
    float m = fmaxf(fmaxf(v.x, v.y), fmaxf(v.z, v.w));
    red[t] = m;
    __syncthreads();
#pragma unroll
    for (int s = 128; s > 0; s >>= 1) {
        if (t < s) red[t] = fmaxf(red[t], red[t + s]);
        __syncthreads();
    }
    m = red[0];
    __syncthreads();

    v.x = __expf(v.x - m); v.y = __expf(v.y - m);
    v.z = __expf(v.z - m); v.w = __expf(v.w - m);
    red[t] = v.x + v.y + v.z + v.w;
    __syncthreads();
#pragma unroll
    for (int s = 128; s > 0; s >>= 1) {
        if (t < s) red[t] += red[t + s];
        __syncthreads();
    }
    float inv = 1.f / red[0];
    v.x *= inv; v.y *= inv; v.z *= inv; v.w *= inv;
    *(float4*)(p + t * 4) = v;
}

// ---------------- out = LayerNorm(a + b) over 512 features ----------------
__global__ void add_ln(const float* __restrict__ a, const float* __restrict__ b,
                       const float* __restrict__ gamma, const float* __restrict__ beta,
                       float* __restrict__ out) {
    long long row = blockIdx.x;
    int t = threadIdx.x;                       // 128 threads x 4 elems
    const float4 va = ((const float4*)(a + row * 512))[t];
    const float4 vb = ((const float4*)(b + row * 512))[t];
    float x0 = va.x + vb.x, x1 = va.y + vb.y, x2 = va.z + vb.z, x3 = va.w + vb.w;

    __shared__ float red[128];
    red[t] = x0 + x1 + x2 + x3;
    __syncthreads();
#pragma unroll
    for (int s = 64; s > 0; s >>= 1) {
        if (t < s) red[t] += red[t + s];
        __syncthreads();
    }
    float mean = red[0] * (1.f / 512.f);
    __syncthreads();

    float d0 = x0 - mean, d1 = x1 - mean, d2 = x2 - mean, d3 = x3 - mean;
    red[t] = d0 * d0 + d1 * d1 + d2 * d2 + d3 * d3;
    __syncthreads();
#pragma unroll
    for (int s = 64; s > 0; s >>= 1) {
        if (t < s) red[t] += red[t + s];
        __syncthreads();
    }
    float var = red[0] * (1.f / 512.f);
    float inv = rsqrtf(var + LN_EPS);

    const float4 g = ((const float4*)gamma)[t];
    const float4 be = ((const float4*)beta)[t];
    float4 o;
    o.x = g.x * (d0 * inv) + be.x;
    o.y = g.y * (d1 * inv) + be.y;
    o.z = g.z * (d2 * inv) + be.z;
    o.w = g.w * (d3 * inv) + be.w;
    ((float4*)(out + row * 512))[t] = o;
}

// ---------------- launch ----------------
extern "C" void kernel_launch(void* const* d_in, const int* in_sizes, int n_in,
                              void* d_out, int out_size) {
    const float* x      = (const float*)d_in[0];
    const float* qw     = (const float*)d_in[1];
    const float* kw     = (const float*)d_in[2];
    const float* vw     = (const float*)d_in[3];
    const float* lw     = (const float*)d_in[4];
    const float* gamma1 = (const float*)d_in[5];
    const float* beta1  = (const float*)d_in[6];
    const float* w1     = (const float*)d_in[7];
    const float* b1     = (const float*)d_in[8];
    const float* w2     = (const float*)d_in[9];
    const float* b2     = (const float*)d_in[10];
    const float* gamma2 = (const float*)d_in[11];
    const float* beta2  = (const float*)d_in[12];
    float* out = (float*)d_out;

    float *Wq, *Wk, *Wv, *Q, *Kb, *V, *S, *A, *Mha, *H, *F1, *F2;
    cudaGetSymbolAddress((void**)&Wq,  g_Wq);
    cudaGetSymbolAddress((void**)&Wk,  g_Wk);
    cudaGetSymbolAddress((void**)&Wv,  g_Wv);
    cudaGetSymbolAddress((void**)&Q,   g_Q);
    cudaGetSymbolAddress((void**)&Kb,  g_Kb);
    cudaGetSymbolAddress((void**)&V,   g_V);
    cudaGetSymbolAddress((void**)&S,   g_S);
    cudaGetSymbolAddress((void**)&A,   g_A);
    cudaGetSymbolAddress((void**)&Mha, g_Mha);
    cudaGetSymbolAddress((void**)&H,   g_H);
    cudaGetSymbolAddress((void**)&F1,  g_F1);
    cudaGetSymbolAddress((void**)&F2,  g_F2);

    dim3 blk(256);

    // pack weights: [H,D,U] -> [D,H*U]
    pack_w<<<(8*512*64 + 255)/256, 256>>>(qw, Wq, 8, 512, 64);
    pack_w<<<(8*512*64 + 255)/256, 256>>>(kw, Wk, 8, 512, 64);
    pack_w<<<(8*512*512 + 255)/256, 256>>>(vw, Wv, 8, 512, 512);

    // Q = x @ Wq : [8192,512]
    gemm128<false><<<dim3(4, 64, 1), blk>>>(x, Wq, Q, 8192, 512, 512, 512, 512, 512,
                                            0, 0, 0, 0, 0, 0, 1, nullptr, 0);
    // K = x @ Wk
    gemm128<false><<<dim3(4, 64, 1), blk>>>(x, Wk, Kb, 8192, 512, 512, 512, 512, 512,
                                            0, 0, 0, 0, 0, 0, 1, nullptr, 0);
    // V = x @ Wv : [8192,4096]
    gemm128<false><<<dim3(32, 64, 1), blk>>>(x, Wv, V, 8192, 4096, 512, 512, 4096, 4096,
                                             0, 0, 0, 0, 0, 0, 1, nullptr, 0);

    // scores[z] = Q_bh @ K_bh^T : z=(b,h), NT, [1024,1024], K=64
    gemm128<true><<<dim3(8, 8, 64), blk>>>(Q, Kb, S, 1024, 1024, 64, 512, 512, 1024,
                                           1024LL*512, 64, 1024LL*512, 64,
                                           8LL*1024*1024, 1024LL*1024, 8, nullptr, 0);

    // softmax(scale * scores) rowwise
    softmax_1024<<<64 * 1024, 256>>>(S, 1.0f / sqrtf(512.0f));

    // attn[z] = P @ V_bh  -> directly into concat-head layout [8192, 4096]
    gemm128<false><<<dim3(4, 8, 64), blk>>>(S, V, A, 1024, 512, 1024, 1024, 4096, 4096,
                                            8LL*1024*1024, 1024LL*1024,
                                            1024LL*4096, 512,
                                            1024LL*4096, 512, 8, nullptr, 0);

    // mha = A @ lw : [8192,512]
    gemm128<false><<<dim3(4, 64, 1), blk>>>(A, lw, Mha, 8192, 512, 4096, 4096, 512, 512,
                                            0, 0, 0, 0, 0, 0, 1, nullptr, 0);

    // h = LN(x + mha)
    add_ln<<<8192, 128>>>(x, Mha, gamma1, beta1, H);

    // F1 = relu(h @ w1 + b1) : [8192,2048]
    gemm128<false><<<dim3(16, 64, 1), blk>>>(H, w1, F1, 8192, 2048, 512, 512, 2048, 2048,
                                             0, 0, 0, 0, 0, 0, 1, b1, 1);

    // F2 = F1 @ w2 + b2 : [8192,512]
    gemm128<false><<<dim3(4, 64, 1), blk>>>(F1, w2, F2, 8192, 512, 2048, 2048, 512, 512,
                                            0, 0, 0, 0, 0, 0, 1, b2, 0);

    // out = LN(h + F2)
    add_ln<<<8192, 128>>>(H, F2, gamma2, beta2, out);
}

// round 3
// speedup vs baseline: 2.0705x; 2.0705x over previous
#include <cuda_runtime.h>
#include <math.h>

// ---------------- problem constants ----------------
#define D_MODEL 512
#define SEQ     1024
#define BATCH   8
#define NHEADS  8
#define UDIM    64
#define FF      2048
#define TOK     (BATCH*SEQ)          // 8192
#define LN_EPS  1e-3f

// ---------------- scratch (static device, allocation-guard safe) -------------
__device__ float g_Wq[D_MODEL*D_MODEL];
__device__ float g_Wk[D_MODEL*D_MODEL];
__device__ float g_Wv[D_MODEL*NHEADS*D_MODEL];
__device__ float g_Q [TOK*D_MODEL];
__device__ float g_Kb[TOK*D_MODEL];
__device__ float g_V [TOK*NHEADS*D_MODEL];
__device__ float g_S [(size_t)BATCH*NHEADS*SEQ*SEQ];
__device__ float g_A [TOK*NHEADS*D_MODEL];
__device__ float g_Mha[TOK*D_MODEL];
__device__ float g_H [TOK*D_MODEL];
__device__ float g_F1[TOK*FF];
__device__ float g_F2[TOK*D_MODEL];

// ---------------- weight pack: [H,D,U] -> [D, H*U] ----------------
__global__ void pack_w(const float* __restrict__ in, float* __restrict__ out,
                       int H, int D, int U) {
    int i = blockIdx.x * blockDim.x + threadIdx.x;
    int total = H * D * U;
    if (i >= total) return;
    int u = i % U;
    int d = (i / U) % D;
    int h = i / (U * D);
    out[d * (H * U) + h * U + u] = in[i];
}

// ---------------- tf32 tensor-core GEMM  128x128x16, 256 thr ----------------
// C[z] = A[z] @ B[z](^T)   via mma.sync.m16n8k8.tf32, fp32 accumulate.
// smem staged k-major [16][132] so every fragment LDS is conflict-free.
// requires: M%128==0, N%128==0, K%16==0.
#define BMP 132

template<bool TRANSB>
__global__ void __launch_bounds__(256) gemm_tc(
    const float* __restrict__ A, const float* __restrict__ B, float* __restrict__ C,
    int M, int N, int K, int lda, int ldb, int ldc,
    long long aOut, long long aIn, long long bOut, long long bIn,
    long long cOut, long long cIn, int HB,
    const float* __restrict__ bias, int relu)
{
    int z  = blockIdx.z;
    int zo = z / HB, zi = z % HB;
    A += zo * aOut + (long long)zi * aIn;
    B += zo * bOut + (long long)zi * bIn;
    C += zo * cOut + (long long)zi * cIn;

    __shared__ float As[2][16][BMP];
    __shared__ float Bs[2][16][BMP];

    const int tid  = threadIdx.x;
    const int lane = tid & 31;
    const int wid  = tid >> 5;
    const int wm   = wid >> 2;          // 0..1  (64-row slab)
    const int wn   = wid & 3;           // 0..3  (32-col slab)
    const int g    = lane >> 2;         // 0..7
    const int tig  = lane & 3;          // 0..3

    const int bm = blockIdx.y * 128;
    const int bn = blockIdx.x * 128;

    // ---- gmem loader mappings ----
    const int arow = tid >> 1;          // 0..127
    const int ac8  = (tid & 1) * 8;     // 0 or 8
    const float* Ag = A + (long long)(bm + arow) * lda + ac8;

    const float* Bg;
    int brow = 0, bcol = 0;
    if (TRANSB) {
        Bg = B + (long long)(bn + arow) * ldb + ac8;   // transpose-load like A
    } else {
        brow = tid >> 4;                // 0..15
        bcol = (tid & 15) * 8;          // 0..120
        Bg = B + (long long)brow * ldb + bn + bcol;
    }

    float acc[4][4][4];
#pragma unroll
    for (int mi = 0; mi < 4; mi++)
#pragma unroll
        for (int ni = 0; ni < 4; ni++)
#pragma unroll
            for (int r = 0; r < 4; r++) acc[mi][ni][r] = 0.f;

    // ---- preload tile 0 ----
    {
        float4 a0 = *(const float4*)(Ag);
        float4 a1 = *(const float4*)(Ag + 4);
        As[0][ac8+0][arow]=a0.x; As[0][ac8+1][arow]=a0.y;
        As[0][ac8+2][arow]=a0.z; As[0][ac8+3][arow]=a0.w;
        As[0][ac8+4][arow]=a1.x; As[0][ac8+5][arow]=a1.y;
        As[0][ac8+6][arow]=a1.z; As[0][ac8+7][arow]=a1.w;
        if (TRANSB) {
            float4 b0 = *(const float4*)(Bg);
            float4 b1 = *(const float4*)(Bg + 4);
            Bs[0][ac8+0][arow]=b0.x; Bs[0][ac8+1][arow]=b0.y;
            Bs[0][ac8+2][arow]=b0.z; Bs[0][ac8+3][arow]=b0.w;
            Bs[0][ac8+4][arow]=b1.x; Bs[0][ac8+5][arow]=b1.y;
            Bs[0][ac8+6][arow]=b1.z; Bs[0][ac8+7][arow]=b1.w;
        } else {
            float4 b0 = *(const float4*)(Bg);
            float4 b1 = *(const float4*)(Bg + 4);
            *(float4*)&Bs[0][brow][bcol]     = b0;
            *(float4*)&Bs[0][brow][bcol + 4] = b1;
        }
    }
    __syncthreads();

    int st = 0;
    for (int k0 = 0; k0 < K; k0 += 16) {
        // ---- prefetch next tile into registers (LDG overlapped with MMAs) ----
        float4 pa0, pa1, pb0, pb1;
        bool havenext = (k0 + 16) < K;
        if (havenext) {
            pa0 = *(const float4*)(Ag + k0 + 16);
            pa1 = *(const float4*)(Ag + k0 + 20);
            if (TRANSB) {
                pb0 = *(const float4*)(Bg + k0 + 16);
                pb1 = *(const float4*)(Bg + k0 + 20);
            } else {
                pb0 = *(const float4*)(Bg + (long long)(k0 + 16) * ldb);
                pb1 = *(const float4*)(Bg + (long long)(k0 + 16) * ldb + 4);
            }
        }

        // ---- compute current stage ----
#pragma unroll
        for (int kk = 0; kk < 2; kk++) {
            const int kr = kk * 8 + tig;
            unsigned af[4][4];
            unsigned bf[4][2];
#pragma unroll
            for (int mi = 0; mi < 4; mi++) {
                const int m0 = wm * 64 + mi * 16 + g;
                af[mi][0] = __float_as_uint(As[st][kr    ][m0    ]);
                af[mi][1] = __float_as_uint(As[st][kr    ][m0 + 8]);
                af[mi][2] = __float_as_uint(As[st][kr + 4][m0    ]);
                af[mi][3] = __float_as_uint(As[st][kr + 4][m0 + 8]);
            }
#pragma unroll
            for (int ni = 0; ni < 4; ni++) {
                const int n0 = wn * 32 + ni * 8 + g;
                bf[ni][0] = __float_as_uint(Bs[st][kr    ][n0]);
                bf[ni][1] = __float_as_uint(Bs[st][kr + 4][n0]);
            }
#pragma unroll
            for (int mi = 0; mi < 4; mi++)
#pragma unroll
                for (int ni = 0; ni < 4; ni++) {
                    asm volatile(
                        "mma.sync.aligned.m16n8k8.row.col.f32.tf32.tf32.f32 "
                        "{%0,%1,%2,%3},{%4,%5,%6,%7},{%8,%9},{%0,%1,%2,%3};\n"
                        : "+f"(acc[mi][ni][0]), "+f"(acc[mi][ni][1]),
                          "+f"(acc[mi][ni][2]), "+f"(acc[mi][ni][3])
                        : "r"(af[mi][0]), "r"(af[mi][1]),
                          "r"(af[mi][2]), "r"(af[mi][3]),
                          "r"(bf[ni][0]), "r"(bf[ni][1]));
                }
        }

        // ---- store prefetched tile into other stage ----
        if (havenext) {
            const int so = st ^ 1;
            As[so][ac8+0][arow]=pa0.x; As[so][ac8+1][arow]=pa0.y;
            As[so][ac8+2][arow]=pa0.z; As[so][ac8+3][arow]=pa0.w;
            As[so][ac8+4][arow]=pa1.x; As[so][ac8+5][arow]=pa1.y;
            As[so][ac8+6][arow]=pa1.z; As[so][ac8+7][arow]=pa1.w;
            if (TRANSB) {
                Bs[so][ac8+0][arow]=pb0.x; Bs[so][ac8+1][arow]=pb0.y;
                Bs[so][ac8+2][arow]=pb0.z; Bs[so][ac8+3][arow]=pb0.w;
                Bs[so][ac8+4][arow]=pb1.x; Bs[so][ac8+5][arow]=pb1.y;
                Bs[so][ac8+6][arow]=pb1.z; Bs[so][ac8+7][arow]=pb1.w;
            } else {
                *(float4*)&Bs[so][brow][bcol]     = pb0;
                *(float4*)&Bs[so][brow][bcol + 4] = pb1;
            }
        }
        __syncthreads();
        st ^= 1;
    }

    // ---- epilogue ----
#pragma unroll
    for (int mi = 0; mi < 4; mi++) {
        const int row0 = bm + wm * 64 + mi * 16 + g;
#pragma unroll
        for (int ni = 0; ni < 4; ni++) {
            const int col = bn + wn * 32 + ni * 8 + tig * 2;
            float v0 = acc[mi][ni][0], v1 = acc[mi][ni][1];
            float v2 = acc[mi][ni][2], v3 = acc[mi][ni][3];
            if (bias) {
                float b0 = bias[col], b1 = bias[col + 1];
                v0 += b0; v1 += b1; v2 += b0; v3 += b1;
            }
            if (relu) {
                v0 = fmaxf(v0, 0.f); v1 = fmaxf(v1, 0.f);
                v2 = fmaxf(v2, 0.f); v3 = fmaxf(v3, 0.f);
            }
            *(float2*)(C + (long long)row0       * ldc + col) = make_float2(v0, v1);
            *(float2*)(C + (long long)(row0 + 8) * ldc + col) = make_float2(v2, v3);
        }
    }
}

// ---------------- row softmax over 1024 cols (with scale) ----------------
__global__ void softmax_1024(float* __restrict__ S, float scale) {
    long long row = blockIdx.x;
    float* p = S + row * 1024;
    int t = threadIdx.x;
    float4 v = *(float4*)(p + t * 4);
    v.x *= scale; v.y *= scale; v.z *= scale; v.w *= scale;

    __shared__ float red[256];
    float m = fmaxf(fmaxf(v.x, v.y), fmaxf(v.z, v.w));
    red[t] = m;
    __syncthreads();
#pragma unroll
    for (int s = 128; s > 0; s >>= 1) {
        if (t < s) red[t] = fmaxf(red[t], red[t + s]);
        __syncthreads();
    }
    m = red[0];
    __syncthreads();

    v.x = __expf(v.x - m); v.y = __expf(v.y - m);
    v.z = __expf(v.z - m); v.w = __expf(v.w - m);
    red[t] = v.x + v.y + v.z + v.w;
    __syncthreads();
#pragma unroll
    for (int s = 128; s > 0; s >>= 1) {
        if (t < s) red[t] += red[t + s];
        __syncthreads();
    }
    float inv = 1.f / red[0];
    v.x *= inv; v.y *= inv; v.z *= inv; v.w *= inv;
    *(float4*)(p + t * 4) = v;
}

// ---------------- out = LayerNorm(a + b) over 512 features ----------------
__global__ void add_ln(const float* __restrict__ a, const float* __restrict__ b,
                       const float* __restrict__ gamma, const float* __restrict__ beta,
                       float* __restrict__ out) {
    long long row = blockIdx.x;
    int t = threadIdx.x;
    const float4 va = ((const float4*)(a + row * 512))[t];
    const float4 vb = ((const float4*)(b + row * 512))[t];
    float x0 = va.x + vb.x, x1 = va.y + vb.y, x2 = va.z + vb.z, x3 = va.w + vb.w;

    __shared__ float red[128];
    red[t] = x0 + x1 + x2 + x3;
    __syncthreads();
#pragma unroll
    for (int s = 64; s > 0; s >>= 1) {
        if (t < s) red[t] += red[t + s];
        __syncthreads();
    }
    float mean = red[0] * (1.f / 512.f);
    __syncthreads();

    float d0 = x0 - mean, d1 = x1 - mean, d2 = x2 - mean, d3 = x3 - mean;
    red[t] = d0 * d0 + d1 * d1 + d2 * d2 + d3 * d3;
    __syncthreads();
#pragma unroll
    for (int s = 64; s > 0; s >>= 1) {
        if (t < s) red[t] += red[t + s];
        __syncthreads();
    }
    float var = red[0] * (1.f / 512.f);
    float inv = rsqrtf(var + LN_EPS);

    const float4 g = ((const float4*)gamma)[t];
    const float4 be = ((const float4*)beta)[t];
    float4 o;
    o.x = g.x * (d0 * inv) + be.x;
    o.y = g.y * (d1 * inv) + be.y;
    o.z = g.z * (d2 * inv) + be.z;
    o.w = g.w * (d3 * inv) + be.w;
    ((float4*)(out + row * 512))[t] = o;
}

// ---------------- launch ----------------
extern "C" void kernel_launch(void* const* d_in, const int* in_sizes, int n_in,
                              void* d_out, int out_size) {
    const float* x      = (const float*)d_in[0];
    const float* qw     = (const float*)d_in[1];
    const float* kw     = (const float*)d_in[2];
    const float* vw     = (const float*)d_in[3];
    const float* lw     = (const float*)d_in[4];
    const float* gamma1 = (const float*)d_in[5];
    const float* beta1  = (const float*)d_in[6];
    const float* w1     = (const float*)d_in[7];
    const float* b1     = (const float*)d_in[8];
    const float* w2     = (const float*)d_in[9];
    const float* b2     = (const float*)d_in[10];
    const float* gamma2 = (const float*)d_in[11];
    const float* beta2  = (const float*)d_in[12];
    float* out = (float*)d_out;

    float *Wq, *Wk, *Wv, *Q, *Kb, *V, *S, *A, *Mha, *H, *F1, *F2;
    cudaGetSymbolAddress((void**)&Wq,  g_Wq);
    cudaGetSymbolAddress((void**)&Wk,  g_Wk);
    cudaGetSymbolAddress((void**)&Wv,  g_Wv);
    cudaGetSymbolAddress((void**)&Q,   g_Q);
    cudaGetSymbolAddress((void**)&Kb,  g_Kb);
    cudaGetSymbolAddress((void**)&V,   g_V);
    cudaGetSymbolAddress((void**)&S,   g_S);
    cudaGetSymbolAddress((void**)&A,   g_A);
    cudaGetSymbolAddress((void**)&Mha, g_Mha);
    cudaGetSymbolAddress((void**)&H,   g_H);
    cudaGetSymbolAddress((void**)&F1,  g_F1);
    cudaGetSymbolAddress((void**)&F2,  g_F2);

    dim3 blk(256);

    pack_w<<<(8*512*64 + 255)/256, 256>>>(qw, Wq, 8, 512, 64);
    pack_w<<<(8*512*64 + 255)/256, 256>>>(kw, Wk, 8, 512, 64);
    pack_w<<<(8*512*512 + 255)/256, 256>>>(vw, Wv, 8, 512, 512);

    // Q = x @ Wq : [8192,512]
    gemm_tc<false><<<dim3(4, 64, 1), blk>>>(x, Wq, Q, 8192, 512, 512, 512, 512, 512,
                                            0, 0, 0, 0, 0, 0, 1, nullptr, 0);
    // K = x @ Wk
    gemm_tc<false><<<dim3(4, 64, 1), blk>>>(x, Wk, Kb, 8192, 512, 512, 512, 512, 512,
                                            0, 0, 0, 0, 0, 0, 1, nullptr, 0);
    // V = x @ Wv : [8192,4096]
    gemm_tc<false><<<dim3(32, 64, 1), blk>>>(x, Wv, V, 8192, 4096, 512, 512, 4096, 4096,
                                             0, 0, 0, 0, 0, 0, 1, nullptr, 0);

    // scores[z] = Q_bh @ K_bh^T : z=(b,h), NT, [1024,1024], K=64
    gemm_tc<true><<<dim3(8, 8, 64), blk>>>(Q, Kb, S, 1024, 1024, 64, 512, 512, 1024,
                                           1024LL*512, 64, 1024LL*512, 64,
                                           8LL*1024*1024, 1024LL*1024, 8, nullptr, 0);

    softmax_1024<<<64 * 1024, 256>>>(S, 1.0f / sqrtf(512.0f));

    // attn[z] = P @ V_bh -> concat-head layout [8192,4096]
    gemm_tc<false><<<dim3(4, 8, 64), blk>>>(S, V, A, 1024, 512, 1024, 1024, 4096, 4096,
                                            8LL*1024*1024, 1024LL*1024,
                                            1024LL*4096, 512,
                                            1024LL*4096, 512, 8, nullptr, 0);

    // mha = A @ lw : [8192,512]
    gemm_tc<false><<<dim3(4, 64, 1), blk>>>(A, lw, Mha, 8192, 512, 4096, 4096, 512, 512,
                                            0, 0, 0, 0, 0, 0, 1, nullptr, 0);

    add_ln<<<8192, 128>>>(x, Mha, gamma1, beta1, H);

    // F1 = relu(h @ w1 + b1) : [8192,2048]
    gemm_tc<false><<<dim3(16, 64, 1), blk>>>(H, w1, F1, 8192, 2048, 512, 512, 2048, 2048,
                                             0, 0, 0, 0, 0, 0, 1, b1, 1);

    // F2 = F1 @ w2 + b2 : [8192,512]
    gemm_tc<false><<<dim3(4, 64, 1), blk>>>(F1, w2, F2, 8192, 512, 2048, 2048, 512, 512,
                                            0, 0, 0, 0, 0, 0, 1, b2, 0);

    add_ln<<<8192, 128>>>(H, F2, gamma2, beta2, out);
}